// round 15
// baseline (speedup 1.0000x reference)
#include <cuda_runtime.h>
#include <cuda_fp16.h>
#include <cstdint>

#define GRIDX 128
#define NPTS (GRIDX * GRIDX)
#define HID 64
#define BATCH 64
#define TILE_M 128
#define TILES_PER_CTA 8
#define CTAS_PER_BATCH 16            // 16 * 8 * 128 = 16384 points per batch
#define NCTAS (BATCH * CTAS_PER_BATCH)
#define THREADS 128

// SMEM offsets from 1024-aligned base
#define SM_B 0                       // B2: 64 rows(n) x 128B (k=j cols, swizzled), fp16
#define SM_SQ 8192                   // s-quads: 128 x 16B
#define SM_WS 10240                  // wsum[4]
#define SMEM_BYTES (10240 + 64 + 1024)

#define SWZ(o) ((o) ^ (((o) >> 3) & 0x70))
#define F16_ONE_LO 0x00003C00u       // f16x2 {hi=0, lo=1.0}

__device__ float g_partials[NCTAS];
__device__ int g_count[BATCH];       // zero-init; self-resets each launch

static __device__ __forceinline__ uint32_t smem_u32(const void* p) {
    uint32_t a;
    asm("{ .reg .u64 t; cvta.to.shared.u64 t, %1; cvt.u32.u64 %0, t; }" : "=r"(a) : "l"(p));
    return a;
}
static __device__ __forceinline__ void sts32(uint32_t addr, uint32_t v) {
    asm volatile("st.shared.b32 [%0], %1;" :: "r"(addr), "r"(v) : "memory");
}
static __device__ __forceinline__ uint32_t cvt_f16x2(float hi, float lo) {
    uint32_t r;
    asm("cvt.rn.f16x2.f32 %0, %1, %2;" : "=r"(r) : "f"(hi), "f"(lo));
    return r;
}
static __device__ __forceinline__ uint32_t relu2(uint32_t v) {
    uint32_t r;
    asm("max.f16x2 %0, %1, %2;" : "=r"(r) : "r"(v), "r"(0u));
    return r;
}
static __device__ __forceinline__ uint32_t hadd2(uint32_t a, uint32_t b) {
    uint32_t r;
    asm("add.f16x2 %0, %1, %2;" : "=r"(r) : "r"(a), "r"(b));
    return r;
}
static __device__ __forceinline__ float f16lo_f(uint32_t v) {
    return __half2float(__ushort_as_half((unsigned short)(v & 0xffff)));
}
static __device__ __forceinline__ float f16hi_f(uint32_t v) {
    return __half2float(__ushort_as_half((unsigned short)(v >> 16)));
}
static __device__ __forceinline__ void ldsm_x4(uint32_t addr, uint32_t& r0, uint32_t& r1,
                                               uint32_t& r2, uint32_t& r3) {
    asm volatile("ldmatrix.sync.aligned.m8n8.x4.shared.b16 {%0,%1,%2,%3}, [%4];"
                 : "=r"(r0), "=r"(r1), "=r"(r2), "=r"(r3) : "r"(addr));
}
static __device__ __forceinline__ void mma16808_f16z(uint32_t* d, const uint32_t* a, uint32_t b) {
    asm volatile(
        "mma.sync.aligned.m16n8k8.row.col.f16.f16.f16.f16 "
        "{%0,%1}, {%2,%3}, {%4}, {%5,%5};"
        : "=r"(d[0]), "=r"(d[1])
        : "r"(a[0]), "r"(a[1]), "r"(b), "r"(0u));
}
static __device__ __forceinline__ void mma16816_f16c(uint32_t* d, const uint32_t* a,
                                                     const uint32_t* b, uint32_t c) {
    asm volatile(
        "mma.sync.aligned.m16n8k16.row.col.f16.f16.f16.f16 "
        "{%0,%1}, {%2,%3,%4,%5}, {%6,%7}, {%8,%8};"
        : "=r"(d[0]), "=r"(d[1])
        : "r"(a[0]), "r"(a[1]), "r"(a[2]), "r"(a[3]), "r"(b[0]), "r"(b[1]), "r"(c));
}
static __device__ __forceinline__ void mma16816_f16acc(uint32_t* d, const uint32_t* a,
                                                       const uint32_t* b) {
    asm volatile(
        "mma.sync.aligned.m16n8k16.row.col.f16.f16.f16.f16 "
        "{%0,%1}, {%2,%3,%4,%5}, {%6,%7}, {%0,%1};"
        : "+r"(d[0]), "+r"(d[1])
        : "r"(a[0]), "r"(a[1]), "r"(a[2]), "r"(a[3]), "r"(b[0]), "r"(b[1]));
}
static __device__ __forceinline__ void mma16816_acc(float* c, const uint32_t* a,
                                                    const uint32_t* b) {
    asm volatile(
        "mma.sync.aligned.m16n8k16.row.col.f32.f16.f16.f32 "
        "{%0,%1,%2,%3}, {%4,%5,%6,%7}, {%8,%9}, {%0,%1,%2,%3};"
        : "+f"(c[0]), "+f"(c[1]), "+f"(c[2]), "+f"(c[3])
        : "r"(a[0]), "r"(a[1]), "r"(a[2]), "r"(a[3]), "r"(b[0]), "r"(b[1]));
}
static __device__ __forceinline__ void mma16816_z(float* d, const uint32_t* a,
                                                  const uint32_t* b) {
    asm volatile(
        "mma.sync.aligned.m16n8k16.row.col.f32.f16.f16.f32 "
        "{%0,%1,%2,%3}, {%4,%5,%6,%7}, {%8,%9}, {%10,%10,%10,%10};"
        : "=f"(d[0]), "=f"(d[1]), "=f"(d[2]), "=f"(d[3])
        : "r"(a[0]), "r"(a[1]), "r"(a[2]), "r"(a[3]), "r"(b[0]), "r"(b[1]),
          "f"(0.0f));
}

__global__ __launch_bounds__(THREADS, 4)
void gauge_tc(const float* __restrict__ x, const float* __restrict__ H,
              const float* __restrict__ W_emb, const float* __restrict__ b_emb,
              const float* __restrict__ W_hid, const float* __restrict__ b_hid,
              const float* __restrict__ W_post, const float* __restrict__ b_post,
              float* __restrict__ out) {
    extern __shared__ __align__(1024) char smraw[];
    const uint32_t sb0 = smem_u32(smraw);
    const uint32_t sb = (sb0 + 1023u) & ~1023u;
    char* smc = smraw + (sb - sb0);

    const int tid = threadIdx.x;
    const int wid = tid >> 5;
    const int lid = tid & 31;

    // Build B2 tile in smem: Bsm[n][j] = fp16(W_hid[j][n]), swizzled 128B rows.
    #pragma unroll
    for (int kq = 0; kq < 16; kq++) {
        const int idx = tid + kq * 128;
        const int n = idx & 63;
        const int jp = idx >> 6;
        const float w0 = __ldg(W_hid + (2 * jp) * HID + n);
        const float w1 = __ldg(W_hid + (2 * jp + 1) * HID + n);
        sts32(sb + SM_B + SWZ((uint32_t)(n * 128 + jp * 4)), cvt_f16x2(w1, w0));
    }
    __syncthreads();

    // Lane geometry
    const int r4 = lid >> 2;
    const int q4 = lid & 3;
    const int kk = q4 * 2;
    const uint32_t skoff = (uint32_t)((kk & 2) * 4);

    // B-fragment lane addressing
    const int amat = lid >> 3;
    const int bn_half = (amat >> 1);
    const int bcol_half = (amat & 1) * 16;
    const int bn_sub = lid & 7;

    // Hoisted B2 fragments for k=0,1 only
    uint32_t bf2h[2][8][2];
    #pragma unroll
    for (int k = 0; k < 2; k++) {
        #pragma unroll
        for (int ntp = 0; ntp < 4; ntp++) {
            const int nt = ntp * 2 + bn_half;
            const int n = nt * 8 + bn_sub;
            const uint32_t cb = (uint32_t)(k * 32 + bcol_half);
            const uint32_t off = (uint32_t)(n * 128) + (cb ^ (((uint32_t)(n & 7)) << 4));
            ldsm_x4(sb + SM_B + off, bf2h[k][2 * ntp][0], bf2h[k][2 * ntp][1],
                    bf2h[k][2 * ntp + 1][0], bf2h[k][2 * ntp + 1][1]);
        }
    }

    // Layer-1 B frags (m16n8k8, K padded to 8): k=0..3 W_emb, k=4 b_emb, k>=5 zero
    uint32_t b1f[8];
    #pragma unroll
    for (int nt = 0; nt < 8; nt++) {
        const int n = nt * 8 + r4;
        float lo_w, hi_w;
        if (q4 < 2)       { lo_w = __ldg(W_emb + kk * HID + n); hi_w = __ldg(W_emb + (kk + 1) * HID + n); }
        else if (q4 == 2) { lo_w = __ldg(b_emb + n); hi_w = 0.0f; }
        else              { lo_w = 0.0f; hi_w = 0.0f; }
        b1f[nt] = cvt_f16x2(hi_w, lo_w);
    }

    // b_hid packed f16x2 at cols nt*8 + kk + {0,1}
    uint32_t bh2[8];
    #pragma unroll
    for (int nt = 0; nt < 8; nt++) {
        const float2 bh = __ldg((const float2*)(b_hid + nt * 8 + kk));
        bh2[nt] = cvt_f16x2(bh.y, bh.x);
    }

    // W_post epilogue B-frags: n=0 col = wp_hi, n=1 col = wp_lo residual, else 0
    uint32_t wpb[4][2];
    #pragma unroll
    for (int k = 0; k < 4; k++) {
        const int j = k * 16 + kk;
        const float2 w0 = __ldg((const float2*)(W_post + j));
        const float2 w1 = __ldg((const float2*)(W_post + j + 8));
        const uint32_t h0 = cvt_f16x2(w0.y, w0.x);
        const uint32_t h1 = cvt_f16x2(w1.y, w1.x);
        if (r4 == 0)      { wpb[k][0] = h0; wpb[k][1] = h1; }
        else if (r4 == 1) {
            wpb[k][0] = cvt_f16x2(w0.y - f16hi_f(h0), w0.x - f16lo_f(h0));
            wpb[k][1] = cvt_f16x2(w1.y - f16hi_f(h1), w1.x - f16lo_f(h1));
        } else            { wpb[k][0] = 0u; wpb[k][1] = 0u; }
    }
    const float h00 = __ldg(H + 0), h01 = __ldg(H + 1), h10 = __ldg(H + 2), h11 = __ldg(H + 3);

    const int cta = blockIdx.x;
    const int b = cta >> 4;
    const int sub = cta & 15;
    const float2* xb = (const float2*)x + (size_t)b * NPTS;
    const int warpbase = wid * 32;

    float acc_out = 0.0f;

    #pragma unroll 1
    for (int tt = 0; tt < TILES_PER_CTA; tt++) {
        const int i = (sub * TILES_PER_CTA + tt) * TILE_M + tid;

        __syncwarp();  // s-quad buffer reuse guard

        // gauge contraction -> s-quad to smem
        {
            const int xc = i & (GRIDX - 1);
            const int yc = i >> 7;
            const int iu = xc + (((yc + 1) & (GRIDX - 1)) << 7);
            const int idn = xc + (((yc - 1) & (GRIDX - 1)) << 7);
            const int il = ((xc - 1) & (GRIDX - 1)) + (yc << 7);
            const int ir = ((xc + 1) & (GRIDX - 1)) + (yc << 7);
            const float2 xi = xb[i];
            const float2 xu = xb[iu], xd = xb[idn], xl = xb[il], xr = xb[ir];
            const float v0 = xi.x * h00 + xi.y * h10;
            const float v1 = xi.x * h01 + xi.y * h11;
            float4 sq;
            sq.x = v0 * xu.x + v1 * xu.y;
            sq.y = v0 * xd.x + v1 * xd.y;
            sq.z = v0 * xl.x + v1 * xl.y;
            sq.w = v0 * xr.x + v1 * xr.y;
            *(float4*)(smc + SM_SQ + tid * 16) = sq;
        }
        __syncwarp();

        float tsum = 0.0f;

        #pragma unroll 1
        for (int mt = 0; mt < 2; mt++) {
            // In-loop ldmatrix for layer-2 k=2,3 B frags
            uint32_t bf23[2][8][2];
            #pragma unroll
            for (int k = 0; k < 2; k++) {
                #pragma unroll
                for (int ntp = 0; ntp < 4; ntp++) {
                    const int nt = ntp * 2 + bn_half;
                    const int n = nt * 8 + bn_sub;
                    const uint32_t cb = (uint32_t)((k + 2) * 32 + bcol_half);
                    const uint32_t off = (uint32_t)(n * 128) + (cb ^ (((uint32_t)(n & 7)) << 4));
                    ldsm_x4(sb + SM_B + off, bf23[k][2 * ntp][0], bf23[k][2 * ntp][1],
                            bf23[k][2 * ntp + 1][0], bf23[k][2 * ntp + 1][1]);
                }
            }

            // A1 fragments (K=8 pad: k4 = 1.0 bias lane, k>=5 = 0)
            const int row0 = warpbase + mt * 16 + r4;
            const float2 sA = *(const float2*)(smc + SM_SQ + row0 * 16 + skoff);
            const float2 sB = *(const float2*)(smc + SM_SQ + (row0 + 8) * 16 + skoff);
            uint32_t a1f[2];
            if (q4 < 2) { a1f[0] = cvt_f16x2(sA.y, sA.x); a1f[1] = cvt_f16x2(sB.y, sB.x); }
            else if (q4 == 2) { a1f[0] = F16_ONE_LO; a1f[1] = F16_ONE_LO; }
            else { a1f[0] = 0u; a1f[1] = 0u; }

            // Layer 1 (fp16 accum): D frags directly in A2 layout; relu in fp16.
            uint32_t af[4][4];
            #pragma unroll
            for (int k = 0; k < 4; k++) {
                uint32_t dA[2], dB[2];
                mma16808_f16z(dA, a1f, b1f[2 * k]);
                mma16808_f16z(dB, a1f, b1f[2 * k + 1]);
                af[k][0] = relu2(dA[0]);
                af[k][1] = relu2(dA[1]);
                af[k][2] = relu2(dB[0]);
                af[k][3] = relu2(dB[1]);
            }

            // Layer 2 + early epilogue, group 1 (nt = 0..3):
            // ds0 depends only on hc[0..3] -> its f32 chain overlaps group-2 L2 MMAs.
            float ds0[4], ds1[4];
            {
                uint32_t hc[4][2];
                #pragma unroll
                for (int nt = 0; nt < 4; nt++) {
                    uint32_t dA[2], dB[2];
                    mma16816_f16c(dA, af[0], bf2h[0][nt], bh2[nt]);
                    mma16816_f16acc(dA, af[1], bf2h[1][nt]);
                    mma16816_f16c(dB, af[2], bf23[0][nt], 0u);
                    mma16816_f16acc(dB, af[3], bf23[1][nt]);
                    hc[nt][0] = relu2(hadd2(dA[0], dB[0]));
                    hc[nt][1] = relu2(hadd2(dA[1], dB[1]));
                }
                const uint32_t a0[4] = {hc[0][0], hc[0][1], hc[1][0], hc[1][1]};
                const uint32_t a1v[4] = {hc[2][0], hc[2][1], hc[3][0], hc[3][1]};
                mma16816_z(ds0, a0, wpb[0]);
                mma16816_acc(ds0, a1v, wpb[1]);
            }
            // Group 2 (nt = 4..7) -> ds1
            {
                uint32_t hc[4][2];
                #pragma unroll
                for (int nt = 4; nt < 8; nt++) {
                    uint32_t dA[2], dB[2];
                    mma16816_f16c(dA, af[0], bf2h[0][nt], bh2[nt]);
                    mma16816_f16acc(dA, af[1], bf2h[1][nt]);
                    mma16816_f16c(dB, af[2], bf23[0][nt], 0u);
                    mma16816_f16acc(dB, af[3], bf23[1][nt]);
                    hc[nt - 4][0] = relu2(hadd2(dA[0], dB[0]));
                    hc[nt - 4][1] = relu2(hadd2(dA[1], dB[1]));
                }
                const uint32_t a2[4] = {hc[0][0], hc[0][1], hc[1][0], hc[1][1]};
                const uint32_t a3[4] = {hc[2][0], hc[2][1], hc[3][0], hc[3][1]};
                mma16816_z(ds1, a2, wpb[2]);
                mma16816_acc(ds1, a3, wpb[3]);
            }
            const float g = ((ds0[0] + ds1[0]) + (ds0[1] + ds1[1])) +
                            ((ds0[2] + ds1[2]) + (ds0[3] + ds1[3]));
            tsum += (q4 == 0) ? g : 0.0f;
        }
        acc_out += tsum;
    }

    // Deterministic reduction: warp -> block -> per-batch last CTA
    float v = acc_out;
    #pragma unroll
    for (int o = 16; o > 0; o >>= 1)
        v += __shfl_down_sync(0xffffffffu, v, o);
    if (lid == 0)
        *(float*)(smc + SM_WS + wid * 4) = v;
    __syncthreads();
    if (tid == 0) {
        float t = 0.0f;
        #pragma unroll
        for (int w = 0; w < 4; w++)
            t += *(float*)(smc + SM_WS + w * 4);
        g_partials[cta] = t;
        __threadfence();
        const int old = atomicAdd(&g_count[b], 1);
        if (old == CTAS_PER_BATCH - 1) {
            g_count[b] = 0;
            __threadfence();
            const volatile float* gp = g_partials;
            float s = 0.0f;
            #pragma unroll
            for (int w = 0; w < CTAS_PER_BATCH; w++)
                s += gp[b * CTAS_PER_BATCH + w];
            out[b] = s + (float)NPTS * __ldg(b_post);
        }
    }
}

extern "C" void kernel_launch(void* const* d_in, const int* in_sizes, int n_in,
                              void* d_out, int out_size) {
    (void)in_sizes; (void)n_in; (void)out_size;
    const float* x      = (const float*)d_in[0];
    const float* H      = (const float*)d_in[1];
    const float* W_emb  = (const float*)d_in[2];
    const float* b_emb  = (const float*)d_in[3];
    const float* W_hid  = (const float*)d_in[4];
    const float* b_hid  = (const float*)d_in[5];
    const float* W_post = (const float*)d_in[6];
    const float* b_post = (const float*)d_in[7];

    cudaFuncSetAttribute(gauge_tc, cudaFuncAttributeMaxDynamicSharedMemorySize, SMEM_BYTES);
    gauge_tc<<<NCTAS, THREADS, SMEM_BYTES>>>(x, H, W_emb, b_emb, W_hid, b_hid,
                                             W_post, b_post, (float*)d_out);
}

// round 16
// speedup vs baseline: 1.1302x; 1.1302x over previous
#include <cuda_runtime.h>
#include <cuda_fp16.h>
#include <cstdint>

#define GRIDX 128
#define NPTS (GRIDX * GRIDX)
#define HID 64
#define BATCH 64
#define TILE_M 128
#define TILES_PER_CTA 8
#define CTAS_PER_BATCH 16            // 16 * 8 * 128 = 16384 points per batch
#define NCTAS (BATCH * CTAS_PER_BATCH)
#define THREADS 128

// SMEM offsets from 1024-aligned base
#define SM_B 0                       // B2: 64 rows(n) x 128B (k=j cols, swizzled), fp16
#define SM_SQ 8192                   // s-quads: 128 x 16B
#define SM_WS 10240                  // wsum[4]
#define SMEM_BYTES (10240 + 64 + 1024)

#define SWZ(o) ((o) ^ (((o) >> 3) & 0x70))
#define F16_ONE_LO 0x00003C00u       // f16x2 {hi=0, lo=1.0}

__device__ float g_partials[NCTAS];
__device__ int g_count[BATCH];       // zero-init; self-resets each launch

static __device__ __forceinline__ uint32_t smem_u32(const void* p) {
    uint32_t a;
    asm("{ .reg .u64 t; cvta.to.shared.u64 t, %1; cvt.u32.u64 %0, t; }" : "=r"(a) : "l"(p));
    return a;
}
static __device__ __forceinline__ void sts32(uint32_t addr, uint32_t v) {
    asm volatile("st.shared.b32 [%0], %1;" :: "r"(addr), "r"(v) : "memory");
}
static __device__ __forceinline__ uint32_t cvt_f16x2(float hi, float lo) {
    uint32_t r;
    asm("cvt.rn.f16x2.f32 %0, %1, %2;" : "=r"(r) : "f"(hi), "f"(lo));
    return r;
}
static __device__ __forceinline__ uint32_t relu2(uint32_t v) {
    uint32_t r;
    asm("max.f16x2 %0, %1, %2;" : "=r"(r) : "r"(v), "r"(0u));
    return r;
}
static __device__ __forceinline__ float f16lo_f(uint32_t v) {
    return __half2float(__ushort_as_half((unsigned short)(v & 0xffff)));
}
static __device__ __forceinline__ float f16hi_f(uint32_t v) {
    return __half2float(__ushort_as_half((unsigned short)(v >> 16)));
}
static __device__ __forceinline__ void ldsm_x4(uint32_t addr, uint32_t& r0, uint32_t& r1,
                                               uint32_t& r2, uint32_t& r3) {
    asm volatile("ldmatrix.sync.aligned.m8n8.x4.shared.b16 {%0,%1,%2,%3}, [%4];"
                 : "=r"(r0), "=r"(r1), "=r"(r2), "=r"(r3) : "r"(addr));
}
static __device__ __forceinline__ void mma16808_f16z(uint32_t* d, const uint32_t* a, uint32_t b) {
    asm volatile(
        "mma.sync.aligned.m16n8k8.row.col.f16.f16.f16.f16 "
        "{%0,%1}, {%2,%3}, {%4}, {%5,%5};"
        : "=r"(d[0]), "=r"(d[1])
        : "r"(a[0]), "r"(a[1]), "r"(b), "r"(0u));
}
// k16 MMA, fp16 accum, C given (bias rows replicated)
static __device__ __forceinline__ void mma16816_f16c(uint32_t* d, const uint32_t* a,
                                                     const uint32_t* b, uint32_t c) {
    asm volatile(
        "mma.sync.aligned.m16n8k16.row.col.f16.f16.f16.f16 "
        "{%0,%1}, {%2,%3,%4,%5}, {%6,%7}, {%8,%8};"
        : "=r"(d[0]), "=r"(d[1])
        : "r"(a[0]), "r"(a[1]), "r"(a[2]), "r"(a[3]), "r"(b[0]), "r"(b[1]), "r"(c));
}
// k16 MMA, fp16 accum in place
static __device__ __forceinline__ void mma16816_f16acc(uint32_t* d, const uint32_t* a,
                                                       const uint32_t* b) {
    asm volatile(
        "mma.sync.aligned.m16n8k16.row.col.f16.f16.f16.f16 "
        "{%0,%1}, {%2,%3,%4,%5}, {%6,%7}, {%0,%1};"
        : "+r"(d[0]), "+r"(d[1])
        : "r"(a[0]), "r"(a[1]), "r"(a[2]), "r"(a[3]), "r"(b[0]), "r"(b[1]));
}
static __device__ __forceinline__ void mma16816_acc(float* c, const uint32_t* a,
                                                    const uint32_t* b) {
    asm volatile(
        "mma.sync.aligned.m16n8k16.row.col.f32.f16.f16.f32 "
        "{%0,%1,%2,%3}, {%4,%5,%6,%7}, {%8,%9}, {%0,%1,%2,%3};"
        : "+f"(c[0]), "+f"(c[1]), "+f"(c[2]), "+f"(c[3])
        : "r"(a[0]), "r"(a[1]), "r"(a[2]), "r"(a[3]), "r"(b[0]), "r"(b[1]));
}
static __device__ __forceinline__ void mma16816_z(float* d, const uint32_t* a,
                                                  const uint32_t* b) {
    asm volatile(
        "mma.sync.aligned.m16n8k16.row.col.f32.f16.f16.f32 "
        "{%0,%1,%2,%3}, {%4,%5,%6,%7}, {%8,%9}, {%10,%10,%10,%10};"
        : "=f"(d[0]), "=f"(d[1]), "=f"(d[2]), "=f"(d[3])
        : "r"(a[0]), "r"(a[1]), "r"(a[2]), "r"(a[3]), "r"(b[0]), "r"(b[1]),
          "f"(0.0f));
}

__global__ __launch_bounds__(THREADS, 5)
void gauge_tc(const float* __restrict__ x, const float* __restrict__ H,
              const float* __restrict__ W_emb, const float* __restrict__ b_emb,
              const float* __restrict__ W_hid, const float* __restrict__ b_hid,
              const float* __restrict__ W_post, const float* __restrict__ b_post,
              float* __restrict__ out) {
    extern __shared__ __align__(1024) char smraw[];
    const uint32_t sb0 = smem_u32(smraw);
    const uint32_t sb = (sb0 + 1023u) & ~1023u;
    char* smc = smraw + (sb - sb0);

    const int tid = threadIdx.x;
    const int wid = tid >> 5;
    const int lid = tid & 31;

    // Build B2 tile in smem: Bsm[n][j] = fp16(W_hid[j][n]), swizzled 128B rows.
    #pragma unroll
    for (int kq = 0; kq < 16; kq++) {
        const int idx = tid + kq * 128;
        const int n = idx & 63;
        const int jp = idx >> 6;
        const float w0 = __ldg(W_hid + (2 * jp) * HID + n);
        const float w1 = __ldg(W_hid + (2 * jp + 1) * HID + n);
        sts32(sb + SM_B + SWZ((uint32_t)(n * 128 + jp * 4)), cvt_f16x2(w1, w0));
    }
    __syncthreads();

    // Lane geometry
    const int r4 = lid >> 2;
    const int q4 = lid & 3;
    const int kk = q4 * 2;
    const uint32_t skoff = (uint32_t)((kk & 2) * 4);

    // B-fragment lane addressing (no hoist: frags loaded per k inside the loop)
    const int amat = lid >> 3;
    const int bn_half = (amat >> 1);
    const int bcol_half = (amat & 1) * 16;
    const int bn_sub = lid & 7;
    // Base swizzled address for this lane's B-frag rows (k term added per step)
    const uint32_t bfrow0 = (uint32_t)(((bn_half * 8 + bn_sub) * 128)) ;
    const uint32_t bfrow1 = (uint32_t)((((2 + bn_half) * 8 + bn_sub) * 128));
    const uint32_t bfrow2 = (uint32_t)((((4 + bn_half) * 8 + bn_sub) * 128));
    const uint32_t bfrow3 = (uint32_t)((((6 + bn_half) * 8 + bn_sub) * 128));
    const uint32_t bsw0 = ((uint32_t)((bn_half * 8 + bn_sub) & 7)) << 4;
    const uint32_t bsw1 = ((uint32_t)(((2 + bn_half) * 8 + bn_sub) & 7)) << 4;
    const uint32_t bsw2 = ((uint32_t)(((4 + bn_half) * 8 + bn_sub) & 7)) << 4;
    const uint32_t bsw3 = ((uint32_t)(((6 + bn_half) * 8 + bn_sub) & 7)) << 4;

    // Layer-1 B frags (m16n8k8, K padded to 8): k=0..3 W_emb, k=4 b_emb, k>=5 zero
    uint32_t b1f[8];
    #pragma unroll
    for (int nt = 0; nt < 8; nt++) {
        const int n = nt * 8 + r4;
        float lo_w, hi_w;
        if (q4 < 2)       { lo_w = __ldg(W_emb + kk * HID + n); hi_w = __ldg(W_emb + (kk + 1) * HID + n); }
        else if (q4 == 2) { lo_w = __ldg(b_emb + n); hi_w = 0.0f; }
        else              { lo_w = 0.0f; hi_w = 0.0f; }
        b1f[nt] = cvt_f16x2(hi_w, lo_w);
    }

    // b_hid packed f16x2 at cols nt*8 + kk + {0,1}
    uint32_t bh2[8];
    #pragma unroll
    for (int nt = 0; nt < 8; nt++) {
        const float2 bh = __ldg((const float2*)(b_hid + nt * 8 + kk));
        bh2[nt] = cvt_f16x2(bh.y, bh.x);
    }

    // W_post epilogue B-frags: n=0 col = wp_hi, n=1 col = wp_lo residual, else 0
    uint32_t wpb[4][2];
    #pragma unroll
    for (int k = 0; k < 4; k++) {
        const int j = k * 16 + kk;
        const float2 w0 = __ldg((const float2*)(W_post + j));
        const float2 w1 = __ldg((const float2*)(W_post + j + 8));
        const uint32_t h0 = cvt_f16x2(w0.y, w0.x);
        const uint32_t h1 = cvt_f16x2(w1.y, w1.x);
        if (r4 == 0)      { wpb[k][0] = h0; wpb[k][1] = h1; }
        else if (r4 == 1) {
            wpb[k][0] = cvt_f16x2(w0.y - f16hi_f(h0), w0.x - f16lo_f(h0));
            wpb[k][1] = cvt_f16x2(w1.y - f16hi_f(h1), w1.x - f16lo_f(h1));
        } else            { wpb[k][0] = 0u; wpb[k][1] = 0u; }
    }
    const float h00 = __ldg(H + 0), h01 = __ldg(H + 1), h10 = __ldg(H + 2), h11 = __ldg(H + 3);

    const int cta = blockIdx.x;
    const int b = cta >> 4;
    const int sub = cta & 15;
    const float2* xb = (const float2*)x + (size_t)b * NPTS;
    const int warpbase = wid * 32;

    float acc_out = 0.0f;

    #pragma unroll 1
    for (int tt = 0; tt < TILES_PER_CTA; tt++) {
        const int i = (sub * TILES_PER_CTA + tt) * TILE_M + tid;

        __syncwarp();  // s-quad buffer reuse guard

        // gauge contraction -> s-quad to smem
        {
            const int xc = i & (GRIDX - 1);
            const int yc = i >> 7;
            const int iu = xc + (((yc + 1) & (GRIDX - 1)) << 7);
            const int idn = xc + (((yc - 1) & (GRIDX - 1)) << 7);
            const int il = ((xc - 1) & (GRIDX - 1)) + (yc << 7);
            const int ir = ((xc + 1) & (GRIDX - 1)) + (yc << 7);
            const float2 xi = xb[i];
            const float2 xu = xb[iu], xd = xb[idn], xl = xb[il], xr = xb[ir];
            const float v0 = xi.x * h00 + xi.y * h10;
            const float v1 = xi.x * h01 + xi.y * h11;
            float4 sq;
            sq.x = v0 * xu.x + v1 * xu.y;
            sq.y = v0 * xd.x + v1 * xd.y;
            sq.z = v0 * xl.x + v1 * xl.y;
            sq.w = v0 * xr.x + v1 * xr.y;
            *(float4*)(smc + SM_SQ + tid * 16) = sq;
        }
        __syncwarp();

        float tsum = 0.0f;

        #pragma unroll 1
        for (int mt = 0; mt < 2; mt++) {
            // A1 fragments (K=8 pad: k4 = 1.0 bias lane, k>=5 = 0)
            const int row0 = warpbase + mt * 16 + r4;
            const float2 sA = *(const float2*)(smc + SM_SQ + row0 * 16 + skoff);
            const float2 sB = *(const float2*)(smc + SM_SQ + (row0 + 8) * 16 + skoff);
            uint32_t a1f[2];
            if (q4 < 2) { a1f[0] = cvt_f16x2(sA.y, sA.x); a1f[1] = cvt_f16x2(sB.y, sB.x); }
            else if (q4 == 2) { a1f[0] = F16_ONE_LO; a1f[1] = F16_ONE_LO; }
            else { a1f[0] = 0u; a1f[1] = 0u; }

            // Layer 1 (fp16 accum): D frags directly in A2 layout; relu in fp16.
            uint32_t af[4][4];
            #pragma unroll
            for (int k = 0; k < 4; k++) {
                uint32_t dA[2], dB[2];
                mma16808_f16z(dA, a1f, b1f[2 * k]);
                mma16808_f16z(dB, a1f, b1f[2 * k + 1]);
                af[k][0] = relu2(dA[0]);
                af[k][1] = relu2(dA[1]);
                af[k][2] = relu2(dB[0]);
                af[k][3] = relu2(dB[1]);
            }

            // Layer 2, k-outer (fp16 accum carried in hc across k; B frags transient)
            uint32_t hc[8][2];
            #pragma unroll
            for (int k = 0; k < 4; k++) {
                uint32_t bf[8][2];
                const uint32_t cb = (uint32_t)(k * 32 + bcol_half);
                ldsm_x4(sb + SM_B + bfrow0 + (cb ^ bsw0), bf[0][0], bf[0][1], bf[1][0], bf[1][1]);
                ldsm_x4(sb + SM_B + bfrow1 + (cb ^ bsw1), bf[2][0], bf[2][1], bf[3][0], bf[3][1]);
                ldsm_x4(sb + SM_B + bfrow2 + (cb ^ bsw2), bf[4][0], bf[4][1], bf[5][0], bf[5][1]);
                ldsm_x4(sb + SM_B + bfrow3 + (cb ^ bsw3), bf[6][0], bf[6][1], bf[7][0], bf[7][1]);
                if (k == 0) {
                    #pragma unroll
                    for (int nt = 0; nt < 8; nt++)
                        mma16816_f16c(hc[nt], af[0], bf[nt], bh2[nt]);
                } else {
                    #pragma unroll
                    for (int nt = 0; nt < 8; nt++)
                        mma16816_f16acc(hc[nt], af[k], bf[nt]);
                }
            }
            #pragma unroll
            for (int nt = 0; nt < 8; nt++) {
                hc[nt][0] = relu2(hc[nt][0]);
                hc[nt][1] = relu2(hc[nt][1]);
            }

            // Epilogue (f32 accum): relu(h2) frags ARE A-frags; dot W_post cols 0/1
            float ds0[4], ds1[4];
            {
                const uint32_t a0[4] = {hc[0][0], hc[0][1], hc[1][0], hc[1][1]};
                const uint32_t a1v[4] = {hc[2][0], hc[2][1], hc[3][0], hc[3][1]};
                const uint32_t a2[4] = {hc[4][0], hc[4][1], hc[5][0], hc[5][1]};
                const uint32_t a3[4] = {hc[6][0], hc[6][1], hc[7][0], hc[7][1]};
                mma16816_z(ds0, a0, wpb[0]);
                mma16816_z(ds1, a1v, wpb[1]);
                mma16816_acc(ds0, a2, wpb[2]);
                mma16816_acc(ds1, a3, wpb[3]);
            }
            const float g = ((ds0[0] + ds1[0]) + (ds0[1] + ds1[1])) +
                            ((ds0[2] + ds1[2]) + (ds0[3] + ds1[3]));
            tsum += (q4 == 0) ? g : 0.0f;
        }
        acc_out += tsum;
    }

    // Deterministic reduction: warp -> block -> per-batch last CTA
    float v = acc_out;
    #pragma unroll
    for (int o = 16; o > 0; o >>= 1)
        v += __shfl_down_sync(0xffffffffu, v, o);
    if (lid == 0)
        *(float*)(smc + SM_WS + wid * 4) = v;
    __syncthreads();
    if (tid == 0) {
        float t = 0.0f;
        #pragma unroll
        for (int w = 0; w < 4; w++)
            t += *(float*)(smc + SM_WS + w * 4);
        g_partials[cta] = t;
        __threadfence();
        const int old = atomicAdd(&g_count[b], 1);
        if (old == CTAS_PER_BATCH - 1) {
            g_count[b] = 0;
            __threadfence();
            const volatile float* gp = g_partials;
            float s = 0.0f;
            #pragma unroll
            for (int w = 0; w < CTAS_PER_BATCH; w++)
                s += gp[b * CTAS_PER_BATCH + w];
            out[b] = s + (float)NPTS * __ldg(b_post);
        }
    }
}

extern "C" void kernel_launch(void* const* d_in, const int* in_sizes, int n_in,
                              void* d_out, int out_size) {
    (void)in_sizes; (void)n_in; (void)out_size;
    const float* x      = (const float*)d_in[0];
    const float* H      = (const float*)d_in[1];
    const float* W_emb  = (const float*)d_in[2];
    const float* b_emb  = (const float*)d_in[3];
    const float* W_hid  = (const float*)d_in[4];
    const float* b_hid  = (const float*)d_in[5];
    const float* W_post = (const float*)d_in[6];
    const float* b_post = (const float*)d_in[7];

    cudaFuncSetAttribute(gauge_tc, cudaFuncAttributeMaxDynamicSharedMemorySize, SMEM_BYTES);
    gauge_tc<<<NCTAS, THREADS, SMEM_BYTES>>>(x, H, W_emb, b_emb, W_hid, b_hid,
                                             W_post, b_post, (float*)d_out);
}